// round 1
// baseline (speedup 1.0000x reference)
#include <cuda_runtime.h>
#include <math.h>

// Problem shape (fixed)
constexpr int B_ = 4, T_ = 2048, C_ = 1024, H_ = 16, D_ = 64;
constexpr int M_ = B_ * T_;  // 8192

// Scratch (allocations are forbidden; use __device__ globals)
__device__ float g_q[M_ * C_];
__device__ float g_k[M_ * C_];
__device__ float g_v[M_ * C_];
__device__ float g_y[M_ * C_];

// ---------------------------------------------------------------------------
// GEMM: out[m,n] = sum_k A[m,k] * W[n,k] + bias[n]   (A: MxK, W: NxK row-major)
// 128x128 block tile, BK=16, 256 threads, 8x8 per-thread microtile.
// ---------------------------------------------------------------------------
constexpr int GBM = 128, GBN = 128, GBK = 16, GTM = 8, GTN = 8;

__global__ __launch_bounds__(256) void gemm_nt(
    const float* __restrict__ A, const float* __restrict__ W,
    const float* __restrict__ bias, float* __restrict__ out,
    int Mdim, int Ndim, int Kdim)
{
    __shared__ float As[GBK][GBM + 4];
    __shared__ float Bs[GBK][GBN + 4];

    const int tid = threadIdx.x;
    const int ty = tid >> 4, tx = tid & 15;
    const int row0 = blockIdx.y * GBM;
    const int col0 = blockIdx.x * GBN;

    float acc[GTM][GTN];
#pragma unroll
    for (int i = 0; i < GTM; i++)
#pragma unroll
        for (int j = 0; j < GTN; j++) acc[i][j] = 0.f;

    for (int k0 = 0; k0 < Kdim; k0 += GBK) {
        // Load A tile (128x16) and W tile (128x16), transposed into shared.
#pragma unroll
        for (int it = 0; it < 2; it++) {
            int f = tid + it * 256;       // 0..511 float4 slots
            int m = f >> 2, kg = f & 3;   // m: 0..127, kg: 0..3
            float4 va = *reinterpret_cast<const float4*>(
                &A[(size_t)(row0 + m) * Kdim + k0 + kg * 4]);
            As[kg * 4 + 0][m] = va.x; As[kg * 4 + 1][m] = va.y;
            As[kg * 4 + 2][m] = va.z; As[kg * 4 + 3][m] = va.w;
            float4 vb = *reinterpret_cast<const float4*>(
                &W[(size_t)(col0 + m) * Kdim + k0 + kg * 4]);
            Bs[kg * 4 + 0][m] = vb.x; Bs[kg * 4 + 1][m] = vb.y;
            Bs[kg * 4 + 2][m] = vb.z; Bs[kg * 4 + 3][m] = vb.w;
        }
        __syncthreads();

#pragma unroll
        for (int kk = 0; kk < GBK; kk++) {
            float a[GTM], b[GTN];
#pragma unroll
            for (int i = 0; i < GTM; i++) a[i] = As[kk][ty * GTM + i];
#pragma unroll
            for (int j = 0; j < GTN; j++) b[j] = Bs[kk][tx * GTN + j];
#pragma unroll
            for (int i = 0; i < GTM; i++)
#pragma unroll
                for (int j = 0; j < GTN; j++) acc[i][j] += a[i] * b[j];
        }
        __syncthreads();
    }

#pragma unroll
    for (int i = 0; i < GTM; i++) {
        int m = row0 + ty * GTM + i;
#pragma unroll
        for (int j = 0; j < GTN; j++) {
            int n = col0 + tx * GTN + j;
            out[(size_t)m * Ndim + n] = acc[i][j] + bias[n];
        }
    }
}

// ---------------------------------------------------------------------------
// RoPE in place on q and k. Layout [B, T, H, D]; pairs (d, d+32) within head.
// ---------------------------------------------------------------------------
__global__ __launch_bounds__(256) void rope_kernel(float* __restrict__ q,
                                                   float* __restrict__ k)
{
    int idx = blockIdx.x * 256 + threadIdx.x;  // B*T*H*32 = 2^22 threads
    int half = idx & 31;
    int h = (idx >> 5) & 15;
    int t = (idx >> 9) & 2047;
    int b = idx >> 20;

    // alpha = 10000^{-half/32}, computed in double then rounded (match fp32 ref)
    float alpha = (float)exp(-(double)half * (log(10000.0) / 32.0));
    float ang = (float)t * alpha;
    float c = cosf(ang), s = sinf(ang);

    size_t off = ((size_t)b * T_ + t) * C_ + h * D_ + half;
    float xr = q[off], xi = q[off + 32];
    q[off] = xr * c - xi * s;
    q[off + 32] = xr * s + xi * c;
    xr = k[off]; xi = k[off + 32];
    k[off] = xr * c - xi * s;
    k[off + 32] = xr * s + xi * c;
}

// ---------------------------------------------------------------------------
// Flash attention (causal, fp32, online softmax).
// Block: 64 queries x one (b,h). 256 threads: 16x16, each 4x4 microtiles.
// Dynamic smem: Qs, Ks, Vs, Ps each 64 x 68 floats.
// ---------------------------------------------------------------------------
constexpr int ABM = 64, ABN = 64, APAD = 4, ALD = D_ + APAD;  // 68
constexpr size_t ATTN_SMEM = 4 * ABM * ALD * sizeof(float);   // 69632 B

__global__ __launch_bounds__(256) void attn_kernel(
    const float* __restrict__ q, const float* __restrict__ k,
    const float* __restrict__ v, float* __restrict__ y)
{
    extern __shared__ float sm[];
    float* Qs = sm;
    float* Ks = Qs + ABM * ALD;
    float* Vs = Ks + ABN * ALD;
    float* Ps = Vs + ABN * ALD;

    const int tid = threadIdx.x;
    const int ty = tid >> 4, tx = tid & 15;
    const int qb = blockIdx.x;
    const int bh = blockIdx.y;
    const int b = bh >> 4, h = bh & 15;

    const size_t base = ((size_t)b * T_) * C_ + h * D_;
    const float* qp = q + base;
    const float* kp = k + base;
    const float* vp = v + base;
    const int q0 = qb * ABM;
    const float scale = 0.125f;  // 1/sqrt(64)

    // Load Q tile (scaled)
#pragma unroll
    for (int it = 0; it < 4; it++) {
        int f = tid + it * 256;
        int r = f >> 4, dg = f & 15;
        float4 vq = *reinterpret_cast<const float4*>(
            &qp[(size_t)(q0 + r) * C_ + dg * 4]);
        vq.x *= scale; vq.y *= scale; vq.z *= scale; vq.w *= scale;
        *reinterpret_cast<float4*>(&Qs[r * ALD + dg * 4]) = vq;
    }

    float m_old[4], lsum[4], acc[4][4];
#pragma unroll
    for (int i = 0; i < 4; i++) {
        m_old[i] = -1e30f; lsum[i] = 0.f;
#pragma unroll
        for (int j = 0; j < 4; j++) acc[i][j] = 0.f;
    }

    const int nkt = qb + 1;  // causal: only tiles with k0 <= q0
    for (int kt = 0; kt < nkt; kt++) {
        const int k0 = kt * ABN;
        // Load K, V tiles
#pragma unroll
        for (int it = 0; it < 4; it++) {
            int f = tid + it * 256;
            int r = f >> 4, dg = f & 15;
            *reinterpret_cast<float4*>(&Ks[r * ALD + dg * 4]) =
                *reinterpret_cast<const float4*>(&kp[(size_t)(k0 + r) * C_ + dg * 4]);
            *reinterpret_cast<float4*>(&Vs[r * ALD + dg * 4]) =
                *reinterpret_cast<const float4*>(&vp[(size_t)(k0 + r) * C_ + dg * 4]);
        }
        __syncthreads();

        // S = Qs @ Ks^T  (4x4 per thread)
        float s[4][4];
#pragma unroll
        for (int i = 0; i < 4; i++)
#pragma unroll
            for (int j = 0; j < 4; j++) s[i][j] = 0.f;

#pragma unroll
        for (int d = 0; d < D_; d += 4) {
            float4 av[4], bv[4];
#pragma unroll
            for (int i = 0; i < 4; i++)
                av[i] = *reinterpret_cast<const float4*>(&Qs[(ty * 4 + i) * ALD + d]);
#pragma unroll
            for (int j = 0; j < 4; j++)
                bv[j] = *reinterpret_cast<const float4*>(&Ks[(tx * 4 + j) * ALD + d]);
#pragma unroll
            for (int i = 0; i < 4; i++)
#pragma unroll
                for (int j = 0; j < 4; j++)
                    s[i][j] += av[i].x * bv[j].x + av[i].y * bv[j].y +
                               av[i].z * bv[j].z + av[i].w * bv[j].w;
        }

        // Causal mask (diagonal tile only)
        if (kt == qb) {
#pragma unroll
            for (int i = 0; i < 4; i++)
#pragma unroll
                for (int j = 0; j < 4; j++)
                    if (k0 + tx * 4 + j > q0 + ty * 4 + i) s[i][j] = -1e30f;
        }

        // Online softmax (row groups = 16 threads sharing ty; shfl within half-warp)
#pragma unroll
        for (int i = 0; i < 4; i++) {
            float mx = s[i][0];
#pragma unroll
            for (int j = 1; j < 4; j++) mx = fmaxf(mx, s[i][j]);
#pragma unroll
            for (int off = 8; off >= 1; off >>= 1)
                mx = fmaxf(mx, __shfl_xor_sync(0xffffffffu, mx, off));
            float mnew = fmaxf(m_old[i], mx);
            float corr = expf(m_old[i] - mnew);
            float ps = 0.f;
#pragma unroll
            for (int j = 0; j < 4; j++) {
                float p = expf(s[i][j] - mnew);
                s[i][j] = p;
                ps += p;
            }
#pragma unroll
            for (int off = 8; off >= 1; off >>= 1)
                ps += __shfl_xor_sync(0xffffffffu, ps, off);
            lsum[i] = lsum[i] * corr + ps;
#pragma unroll
            for (int j = 0; j < 4; j++) acc[i][j] *= corr;
            m_old[i] = mnew;
        }

        // Store P to shared
#pragma unroll
        for (int i = 0; i < 4; i++)
#pragma unroll
            for (int j = 0; j < 4; j++)
                Ps[(ty * 4 + i) * ALD + tx * 4 + j] = s[i][j];
        __syncthreads();

        // O += P @ V  (each thread: rows ty*4+i, d cols tx*4..tx*4+3)
#pragma unroll 8
        for (int n = 0; n < ABN; n++) {
            float4 vv = *reinterpret_cast<const float4*>(&Vs[n * ALD + tx * 4]);
#pragma unroll
            for (int i = 0; i < 4; i++) {
                float p = Ps[(ty * 4 + i) * ALD + n];
                acc[i][0] += p * vv.x;
                acc[i][1] += p * vv.y;
                acc[i][2] += p * vv.z;
                acc[i][3] += p * vv.w;
            }
        }
        __syncthreads();
    }

    // Write y[b, t, h, d] = acc / l
#pragma unroll
    for (int i = 0; i < 4; i++) {
        float inv = 1.f / lsum[i];
        float4 o;
        o.x = acc[i][0] * inv; o.y = acc[i][1] * inv;
        o.z = acc[i][2] * inv; o.w = acc[i][3] * inv;
        *reinterpret_cast<float4*>(
            &y[base + (size_t)(q0 + ty * 4 + i) * C_ + tx * 4]) = o;
    }
}

// ---------------------------------------------------------------------------
// Launch
// ---------------------------------------------------------------------------
extern "C" void kernel_launch(void* const* d_in, const int* in_sizes, int n_in,
                              void* d_out, int out_size)
{
    const float* x  = (const float*)d_in[0];
    const float* wq = (const float*)d_in[1];
    const float* bq = (const float*)d_in[2];
    const float* wk = (const float*)d_in[3];
    const float* bk = (const float*)d_in[4];
    const float* wv = (const float*)d_in[5];
    const float* bv = (const float*)d_in[6];
    const float* wp = (const float*)d_in[7];
    const float* bp = (const float*)d_in[8];
    float* out = (float*)d_out;

    float *qp, *kp, *vp, *yp;
    cudaGetSymbolAddress((void**)&qp, g_q);
    cudaGetSymbolAddress((void**)&kp, g_k);
    cudaGetSymbolAddress((void**)&vp, g_v);
    cudaGetSymbolAddress((void**)&yp, g_y);

    cudaFuncSetAttribute(attn_kernel,
                         cudaFuncAttributeMaxDynamicSharedMemorySize,
                         (int)ATTN_SMEM);

    dim3 ggrid(C_ / GBN, M_ / GBM);  // (8, 64)
    gemm_nt<<<ggrid, 256>>>(x, wq, bq, qp, M_, C_, C_);
    gemm_nt<<<ggrid, 256>>>(x, wk, bk, kp, M_, C_, C_);
    gemm_nt<<<ggrid, 256>>>(x, wv, bv, vp, M_, C_, C_);

    rope_kernel<<<(B_ * T_ * H_ * 32) / 256, 256>>>(qp, kp);

    dim3 agrid(T_ / ABM, B_ * H_);   // (32, 64)
    attn_kernel<<<agrid, 256, ATTN_SMEM>>>(qp, kp, vp, yp);

    gemm_nt<<<ggrid, 256>>>(yp, wp, bp, out, M_, C_, C_);
}

// round 3
// speedup vs baseline: 1.6660x; 1.6660x over previous
#include <cuda_runtime.h>
#include <cstdint>
#include <math.h>

// Problem shape (fixed)
constexpr int B_ = 4, T_ = 2048, C_ = 1024, H_ = 16, D_ = 64;
constexpr int M_ = B_ * T_;  // 8192

// Scratch (allocations are forbidden; use __device__ globals)
__device__ float g_q[M_ * C_];
__device__ float g_k[M_ * C_];
__device__ float g_v[M_ * C_];
__device__ float g_y[M_ * C_];

// ---------------------------------------------------------------------------
// tf32 helpers (mma.sync path — tcgen05 is not available: harness compiles
// to plain compute_103 PTX, which rejects sm_103a-gated instructions)
// ---------------------------------------------------------------------------
__device__ __forceinline__ uint32_t tf32r(float x) {
    uint32_t u;
    asm("cvt.rna.tf32.f32 %0, %1;" : "=r"(u) : "f"(x));
    return u;
}

__device__ __forceinline__ void mma_tf32(float* c, const uint32_t* a,
                                         const uint32_t* b) {
    asm volatile(
        "mma.sync.aligned.m16n8k8.row.col.f32.tf32.tf32.f32 "
        "{%0,%1,%2,%3}, {%4,%5,%6,%7}, {%8,%9}, {%0,%1,%2,%3};"
        : "+f"(c[0]), "+f"(c[1]), "+f"(c[2]), "+f"(c[3])
        : "r"(a[0]), "r"(a[1]), "r"(a[2]), "r"(a[3]), "r"(b[0]), "r"(b[1]));
}

// ---------------------------------------------------------------------------
// GEMM via mma.sync tf32: out[m,n] = sum_k A[m,k]*W[n,k] + bias[n]
// A: MxK row-major, W: NxK row-major (so B^T is "col" operand directly).
// 128x128 tile, BK=32, 256 threads (8 warps: 2M x 4N), warp tile 64x32.
// SMEM stride 36 floats => conflict-free fragment loads (bank = 4r+c).
// ---------------------------------------------------------------------------
constexpr int BM = 128, BN = 128, BK = 32, LDS_ = 36;
constexpr int TILE_F = 128 * LDS_;                       // floats per operand buf
constexpr int GEMM_SMEM = 2 * 2 * TILE_F * 4;            // 73728 B

__global__ __launch_bounds__(256) void gemm_mma(
    const float* __restrict__ A, const float* __restrict__ W,
    const float* __restrict__ bias, float* __restrict__ out)
{
    extern __shared__ __align__(16) uint32_t smg[];
    uint32_t* As = smg;                     // [2][128][36]
    uint32_t* Bs = smg + 2 * TILE_F;        // [2][128][36]

    const int tid = threadIdx.x;
    const int lane = tid & 31, wid = tid >> 5;
    const int warp_m = wid & 1, warp_n = wid >> 1;   // 2 x 4
    const int row0 = blockIdx.y * BM;
    const int col0 = blockIdx.x * BN;

    const int lrow = tid >> 3, lc4 = tid & 7;        // loader: 32 rows per it? no:
    // each thread loads 4 float4 per operand per chunk: f = tid + it*256
    float acc[4][4][4];
#pragma unroll
    for (int i = 0; i < 4; i++)
#pragma unroll
        for (int j = 0; j < 4; j++)
#pragma unroll
            for (int r = 0; r < 4; r++) acc[i][j][r] = 0.f;

    float4 ra[4], rb[4];

    auto ldg_chunk = [&](int c) {
        const int k0 = c * BK;
#pragma unroll
        for (int it = 0; it < 4; it++) {
            int f = tid + it * 256;              // 0..1023
            int row = f >> 3, c4 = f & 7;
            ra[it] = *reinterpret_cast<const float4*>(
                &A[(size_t)(row0 + row) * C_ + k0 + c4 * 4]);
            rb[it] = *reinterpret_cast<const float4*>(
                &W[(size_t)(col0 + row) * C_ + k0 + c4 * 4]);
        }
    };
    auto sts_chunk = [&](int buf) {
        uint32_t* as = As + buf * TILE_F;
        uint32_t* bs = Bs + buf * TILE_F;
#pragma unroll
        for (int it = 0; it < 4; it++) {
            int f = tid + it * 256;
            int row = f >> 3, c4 = f & 7;
            int o = row * LDS_ + c4 * 4;
            as[o + 0] = tf32r(ra[it].x); as[o + 1] = tf32r(ra[it].y);
            as[o + 2] = tf32r(ra[it].z); as[o + 3] = tf32r(ra[it].w);
            bs[o + 0] = tf32r(rb[it].x); bs[o + 1] = tf32r(rb[it].y);
            bs[o + 2] = tf32r(rb[it].z); bs[o + 3] = tf32r(rb[it].w);
        }
    };

    ldg_chunk(0);
    sts_chunk(0);
    __syncthreads();

    const int NCH = C_ / BK;  // 32
    for (int c = 0; c < NCH; c++) {
        if (c + 1 < NCH) ldg_chunk(c + 1);

        const uint32_t* as = As + (c & 1) * TILE_F;
        const uint32_t* bs = Bs + (c & 1) * TILE_F;
        const int ar = warp_m * 64 + (lane >> 2);     // + mt*16 (+8 for hi)
        const int br = warp_n * 32 + (lane >> 2);     // + nt*8
        const int kc = lane & 3;                      // + kk*8 (+4)

#pragma unroll
        for (int kk = 0; kk < 4; kk++) {
            const int kb = kk * 8 + kc;
            uint32_t af[4][4], bf[4][2];
#pragma unroll
            for (int mt = 0; mt < 4; mt++) {
                const uint32_t* p = as + (ar + mt * 16) * LDS_ + kb;
                af[mt][0] = p[0];
                af[mt][1] = p[8 * LDS_];
                af[mt][2] = p[4];
                af[mt][3] = p[8 * LDS_ + 4];
            }
#pragma unroll
            for (int nt = 0; nt < 4; nt++) {
                const uint32_t* p = bs + (br + nt * 8) * LDS_ + kb;
                bf[nt][0] = p[0];
                bf[nt][1] = p[4];
            }
#pragma unroll
            for (int mt = 0; mt < 4; mt++)
#pragma unroll
                for (int nt = 0; nt < 4; nt++)
                    mma_tf32(acc[mt][nt], af[mt], bf[nt]);
        }
        __syncthreads();
        if (c + 1 < NCH) {
            sts_chunk((c + 1) & 1);
            __syncthreads();
        }
    }

    // Epilogue: bias + direct float2 stores
    const int orow = row0 + warp_m * 64 + (lane >> 2);
    const int ocol = col0 + warp_n * 32 + 2 * (lane & 3);
#pragma unroll
    for (int nt = 0; nt < 4; nt++) {
        const int cg = ocol + nt * 8;
        const float b0 = bias[cg], b1 = bias[cg + 1];
#pragma unroll
        for (int mt = 0; mt < 4; mt++) {
            float2 v0 = make_float2(acc[mt][nt][0] + b0, acc[mt][nt][1] + b1);
            float2 v1 = make_float2(acc[mt][nt][2] + b0, acc[mt][nt][3] + b1);
            *reinterpret_cast<float2*>(&out[(size_t)(orow + mt * 16) * C_ + cg]) = v0;
            *reinterpret_cast<float2*>(&out[(size_t)(orow + mt * 16 + 8) * C_ + cg]) = v1;
        }
    }
}

// ---------------------------------------------------------------------------
// RoPE in place on q and k (fp32 fast path).
// ---------------------------------------------------------------------------
__global__ __launch_bounds__(256) void rope_kernel(float* __restrict__ q,
                                                   float* __restrict__ k)
{
    int idx = blockIdx.x * 256 + threadIdx.x;
    int half = idx & 31;
    int h = (idx >> 5) & 15;
    int t = (idx >> 9) & 2047;
    int b = idx >> 20;

    float alpha = exp2f(-(float)half * 0.41524101186092029f);
    float ang = (float)t * alpha;
    float c = cosf(ang), s = sinf(ang);

    size_t off = ((size_t)b * T_ + t) * C_ + h * D_ + half;
    float xr = q[off], xi = q[off + 32];
    q[off] = xr * c - xi * s;
    q[off + 32] = xr * s + xi * c;
    xr = k[off]; xi = k[off + 32];
    k[off] = xr * c - xi * s;
    k[off + 32] = xr * s + xi * c;
}

// ---------------------------------------------------------------------------
// Flash attention (causal, fp32, online softmax). __expf fast path.
// ---------------------------------------------------------------------------
constexpr int ABM = 64, ABN = 64, APAD = 4, ALD = D_ + APAD;  // 68
constexpr size_t ATTN_SMEM = 4 * ABM * ALD * sizeof(float);   // 69632 B

__global__ __launch_bounds__(256) void attn_kernel(
    const float* __restrict__ q, const float* __restrict__ k,
    const float* __restrict__ v, float* __restrict__ y)
{
    extern __shared__ float sm[];
    float* Qs = sm;
    float* Ks = Qs + ABM * ALD;
    float* Vs = Ks + ABN * ALD;
    float* Ps = Vs + ABN * ALD;

    const int tid = threadIdx.x;
    const int ty = tid >> 4, tx = tid & 15;
    const int qb = blockIdx.x;
    const int bh = blockIdx.y;
    const int b = bh >> 4, h = bh & 15;

    const size_t base = ((size_t)b * T_) * C_ + h * D_;
    const float* qp = q + base;
    const float* kp = k + base;
    const float* vp = v + base;
    const int q0 = qb * ABM;
    const float scale = 0.125f;

#pragma unroll
    for (int it = 0; it < 4; it++) {
        int f = tid + it * 256;
        int r = f >> 4, dg = f & 15;
        float4 vq = *reinterpret_cast<const float4*>(
            &qp[(size_t)(q0 + r) * C_ + dg * 4]);
        vq.x *= scale; vq.y *= scale; vq.z *= scale; vq.w *= scale;
        *reinterpret_cast<float4*>(&Qs[r * ALD + dg * 4]) = vq;
    }

    float m_old[4], lsum[4], acc[4][4];
#pragma unroll
    for (int i = 0; i < 4; i++) {
        m_old[i] = -1e30f; lsum[i] = 0.f;
#pragma unroll
        for (int j = 0; j < 4; j++) acc[i][j] = 0.f;
    }

    const int nkt = qb + 1;
    for (int kt = 0; kt < nkt; kt++) {
        const int k0 = kt * ABN;
#pragma unroll
        for (int it = 0; it < 4; it++) {
            int f = tid + it * 256;
            int r = f >> 4, dg = f & 15;
            *reinterpret_cast<float4*>(&Ks[r * ALD + dg * 4]) =
                *reinterpret_cast<const float4*>(&kp[(size_t)(k0 + r) * C_ + dg * 4]);
            *reinterpret_cast<float4*>(&Vs[r * ALD + dg * 4]) =
                *reinterpret_cast<const float4*>(&vp[(size_t)(k0 + r) * C_ + dg * 4]);
        }
        __syncthreads();

        float s[4][4];
#pragma unroll
        for (int i = 0; i < 4; i++)
#pragma unroll
            for (int j = 0; j < 4; j++) s[i][j] = 0.f;

#pragma unroll
        for (int d = 0; d < D_; d += 4) {
            float4 av[4], bv[4];
#pragma unroll
            for (int i = 0; i < 4; i++)
                av[i] = *reinterpret_cast<const float4*>(&Qs[(ty * 4 + i) * ALD + d]);
#pragma unroll
            for (int j = 0; j < 4; j++)
                bv[j] = *reinterpret_cast<const float4*>(&Ks[(tx * 4 + j) * ALD + d]);
#pragma unroll
            for (int i = 0; i < 4; i++)
#pragma unroll
                for (int j = 0; j < 4; j++)
                    s[i][j] += av[i].x * bv[j].x + av[i].y * bv[j].y +
                               av[i].z * bv[j].z + av[i].w * bv[j].w;
        }

        if (kt == qb) {
#pragma unroll
            for (int i = 0; i < 4; i++)
#pragma unroll
                for (int j = 0; j < 4; j++)
                    if (k0 + tx * 4 + j > q0 + ty * 4 + i) s[i][j] = -1e30f;
        }

#pragma unroll
        for (int i = 0; i < 4; i++) {
            float mx = s[i][0];
#pragma unroll
            for (int j = 1; j < 4; j++) mx = fmaxf(mx, s[i][j]);
#pragma unroll
            for (int off = 8; off >= 1; off >>= 1)
                mx = fmaxf(mx, __shfl_xor_sync(0xffffffffu, mx, off));
            float mnew = fmaxf(m_old[i], mx);
            float corr = __expf(m_old[i] - mnew);
            float ps = 0.f;
#pragma unroll
            for (int j = 0; j < 4; j++) {
                float p = __expf(s[i][j] - mnew);
                s[i][j] = p;
                ps += p;
            }
#pragma unroll
            for (int off = 8; off >= 1; off >>= 1)
                ps += __shfl_xor_sync(0xffffffffu, ps, off);
            lsum[i] = lsum[i] * corr + ps;
#pragma unroll
            for (int j = 0; j < 4; j++) acc[i][j] *= corr;
            m_old[i] = mnew;
        }

#pragma unroll
        for (int i = 0; i < 4; i++)
#pragma unroll
            for (int j = 0; j < 4; j++)
                Ps[(ty * 4 + i) * ALD + tx * 4 + j] = s[i][j];
        __syncthreads();

#pragma unroll 8
        for (int n = 0; n < ABN; n++) {
            float4 vv = *reinterpret_cast<const float4*>(&Vs[n * ALD + tx * 4]);
#pragma unroll
            for (int i = 0; i < 4; i++) {
                float p = Ps[(ty * 4 + i) * ALD + n];
                acc[i][0] += p * vv.x;
                acc[i][1] += p * vv.y;
                acc[i][2] += p * vv.z;
                acc[i][3] += p * vv.w;
            }
        }
        __syncthreads();
    }

#pragma unroll
    for (int i = 0; i < 4; i++) {
        float inv = 1.f / lsum[i];
        float4 o;
        o.x = acc[i][0] * inv; o.y = acc[i][1] * inv;
        o.z = acc[i][2] * inv; o.w = acc[i][3] * inv;
        *reinterpret_cast<float4*>(
            &y[base + (size_t)(q0 + ty * 4 + i) * C_ + tx * 4]) = o;
    }
}

// ---------------------------------------------------------------------------
// Launch
// ---------------------------------------------------------------------------
extern "C" void kernel_launch(void* const* d_in, const int* in_sizes, int n_in,
                              void* d_out, int out_size)
{
    const float* x  = (const float*)d_in[0];
    const float* wq = (const float*)d_in[1];
    const float* bq = (const float*)d_in[2];
    const float* wk = (const float*)d_in[3];
    const float* bk = (const float*)d_in[4];
    const float* wv = (const float*)d_in[5];
    const float* bv = (const float*)d_in[6];
    const float* wp = (const float*)d_in[7];
    const float* bp = (const float*)d_in[8];
    float* out = (float*)d_out;

    float *qp, *kp, *vp, *yp;
    cudaGetSymbolAddress((void**)&qp, g_q);
    cudaGetSymbolAddress((void**)&kp, g_k);
    cudaGetSymbolAddress((void**)&vp, g_v);
    cudaGetSymbolAddress((void**)&yp, g_y);

    cudaFuncSetAttribute(attn_kernel,
                         cudaFuncAttributeMaxDynamicSharedMemorySize,
                         (int)ATTN_SMEM);
    cudaFuncSetAttribute(gemm_mma,
                         cudaFuncAttributeMaxDynamicSharedMemorySize,
                         GEMM_SMEM);

    dim3 ggrid(C_ / BN, M_ / BM);  // (8, 64)
    gemm_mma<<<ggrid, 256, GEMM_SMEM>>>(x, wq, bq, qp);
    gemm_mma<<<ggrid, 256, GEMM_SMEM>>>(x, wk, bk, kp);
    gemm_mma<<<ggrid, 256, GEMM_SMEM>>>(x, wv, bv, vp);

    rope_kernel<<<(B_ * T_ * H_ * 32) / 256, 256>>>(qp, kp);

    dim3 agrid(T_ / ABM, B_ * H_);   // (32, 64)
    attn_kernel<<<agrid, 256, ATTN_SMEM>>>(qp, kp, vp, yp);

    gemm_mma<<<ggrid, 256, GEMM_SMEM>>>(yp, wp, bp, out);
}

// round 7
// speedup vs baseline: 4.0962x; 2.4587x over previous
#include <cuda_runtime.h>
#include <cstdint>
#include <math.h>

// Problem shape (fixed)
constexpr int B_ = 4, T_ = 2048, C_ = 1024, H_ = 16, D_ = 64;
constexpr int M_ = B_ * T_;  // 8192

// Scratch (allocations are forbidden; use __device__ globals)
__device__ float g_q[M_ * C_];
__device__ float g_k[M_ * C_];
__device__ float g_v[M_ * C_];
__device__ float g_y[M_ * C_];

// ---------------------------------------------------------------------------
// tf32 helpers (mma.sync path — tcgen05 unavailable: harness emits compute_103)
// ---------------------------------------------------------------------------
__device__ __forceinline__ uint32_t tf32r(float x) {
    uint32_t u;
    asm("cvt.rna.tf32.f32 %0, %1;" : "=r"(u) : "f"(x));
    return u;
}

__device__ __forceinline__ void mma_tf32(float* c, const uint32_t* a,
                                         const uint32_t* b) {
    asm volatile(
        "mma.sync.aligned.m16n8k8.row.col.f32.tf32.tf32.f32 "
        "{%0,%1,%2,%3}, {%4,%5,%6,%7}, {%8,%9}, {%0,%1,%2,%3};"
        : "+f"(c[0]), "+f"(c[1]), "+f"(c[2]), "+f"(c[3])
        : "r"(a[0]), "r"(a[1]), "r"(a[2]), "r"(a[3]), "r"(b[0]), "r"(b[1]));
}
__device__ __forceinline__ void mma_u(float* c, uint32_t a0, uint32_t a1,
                                      uint32_t a2, uint32_t a3,
                                      uint32_t b0, uint32_t b1) {
    asm volatile(
        "mma.sync.aligned.m16n8k8.row.col.f32.tf32.tf32.f32 "
        "{%0,%1,%2,%3}, {%4,%5,%6,%7}, {%8,%9}, {%0,%1,%2,%3};"
        : "+f"(c[0]), "+f"(c[1]), "+f"(c[2]), "+f"(c[3])
        : "r"(a0), "r"(a1), "r"(a2), "r"(a3), "r"(b0), "r"(b1));
}

// ---------------------------------------------------------------------------
// GEMM via mma.sync tf32: out = A*W^T + bias
// 128x128 tile, BK=32, 256 threads (8 warps: 2M x 4N), warp tile 64x32.
// ---------------------------------------------------------------------------
constexpr int BM = 128, BN = 128, BK = 32, LDS_ = 36;
constexpr int TILE_F = 128 * LDS_;
constexpr int GEMM_SMEM = 2 * 2 * TILE_F * 4;  // 73728 B

__global__ __launch_bounds__(256) void gemm_mma(
    const float* __restrict__ A, const float* __restrict__ W,
    const float* __restrict__ bias, float* __restrict__ out)
{
    extern __shared__ __align__(16) uint32_t smg[];
    uint32_t* As = smg;
    uint32_t* Bs = smg + 2 * TILE_F;

    const int tid = threadIdx.x;
    const int lane = tid & 31, wid = tid >> 5;
    const int warp_m = wid & 1, warp_n = wid >> 1;
    const int row0 = blockIdx.y * BM;
    const int col0 = blockIdx.x * BN;

    float acc[4][4][4];
#pragma unroll
    for (int i = 0; i < 4; i++)
#pragma unroll
        for (int j = 0; j < 4; j++)
#pragma unroll
            for (int r = 0; r < 4; r++) acc[i][j][r] = 0.f;

    float4 ra[4], rb[4];

    auto ldg_chunk = [&](int c) {
        const int k0 = c * BK;
#pragma unroll
        for (int it = 0; it < 4; it++) {
            int f = tid + it * 256;
            int row = f >> 3, c4 = f & 7;
            ra[it] = *reinterpret_cast<const float4*>(
                &A[(size_t)(row0 + row) * C_ + k0 + c4 * 4]);
            rb[it] = *reinterpret_cast<const float4*>(
                &W[(size_t)(col0 + row) * C_ + k0 + c4 * 4]);
        }
    };
    auto sts_chunk = [&](int buf) {
        uint32_t* as = As + buf * TILE_F;
        uint32_t* bs = Bs + buf * TILE_F;
#pragma unroll
        for (int it = 0; it < 4; it++) {
            int f = tid + it * 256;
            int row = f >> 3, c4 = f & 7;
            int o = row * LDS_ + c4 * 4;
            as[o + 0] = tf32r(ra[it].x); as[o + 1] = tf32r(ra[it].y);
            as[o + 2] = tf32r(ra[it].z); as[o + 3] = tf32r(ra[it].w);
            bs[o + 0] = tf32r(rb[it].x); bs[o + 1] = tf32r(rb[it].y);
            bs[o + 2] = tf32r(rb[it].z); bs[o + 3] = tf32r(rb[it].w);
        }
    };

    ldg_chunk(0);
    sts_chunk(0);
    __syncthreads();

    const int NCH = C_ / BK;
    for (int c = 0; c < NCH; c++) {
        if (c + 1 < NCH) ldg_chunk(c + 1);

        const uint32_t* as = As + (c & 1) * TILE_F;
        const uint32_t* bs = Bs + (c & 1) * TILE_F;
        const int ar = warp_m * 64 + (lane >> 2);
        const int br = warp_n * 32 + (lane >> 2);
        const int kc = lane & 3;

#pragma unroll
        for (int kk = 0; kk < 4; kk++) {
            const int kb = kk * 8 + kc;
            uint32_t af[4][4], bf[4][2];
#pragma unroll
            for (int mt = 0; mt < 4; mt++) {
                const uint32_t* p = as + (ar + mt * 16) * LDS_ + kb;
                af[mt][0] = p[0];
                af[mt][1] = p[8 * LDS_];
                af[mt][2] = p[4];
                af[mt][3] = p[8 * LDS_ + 4];
            }
#pragma unroll
            for (int nt = 0; nt < 4; nt++) {
                const uint32_t* p = bs + (br + nt * 8) * LDS_ + kb;
                bf[nt][0] = p[0];
                bf[nt][1] = p[4];
            }
#pragma unroll
            for (int mt = 0; mt < 4; mt++)
#pragma unroll
                for (int nt = 0; nt < 4; nt++)
                    mma_tf32(acc[mt][nt], af[mt], bf[nt]);
        }
        __syncthreads();
        if (c + 1 < NCH) {
            sts_chunk((c + 1) & 1);
            __syncthreads();
        }
    }

    const int orow = row0 + warp_m * 64 + (lane >> 2);
    const int ocol = col0 + warp_n * 32 + 2 * (lane & 3);
#pragma unroll
    for (int nt = 0; nt < 4; nt++) {
        const int cg = ocol + nt * 8;
        const float b0 = bias[cg], b1 = bias[cg + 1];
#pragma unroll
        for (int mt = 0; mt < 4; mt++) {
            float2 v0 = make_float2(acc[mt][nt][0] + b0, acc[mt][nt][1] + b1);
            float2 v1 = make_float2(acc[mt][nt][2] + b0, acc[mt][nt][3] + b1);
            *reinterpret_cast<float2*>(&out[(size_t)(orow + mt * 16) * C_ + cg]) = v0;
            *reinterpret_cast<float2*>(&out[(size_t)(orow + mt * 16 + 8) * C_ + cg]) = v1;
        }
    }
}

// ---------------------------------------------------------------------------
// RoPE in place on q and k (fp32).
// ---------------------------------------------------------------------------
__global__ __launch_bounds__(256) void rope_kernel(float* __restrict__ q,
                                                   float* __restrict__ k)
{
    int idx = blockIdx.x * 256 + threadIdx.x;
    int half = idx & 31;
    int h = (idx >> 5) & 15;
    int t = (idx >> 9) & 2047;
    int b = idx >> 20;

    float alpha = exp2f(-(float)half * 0.41524101186092029f);
    float ang = (float)t * alpha;
    float c = cosf(ang), s = sinf(ang);

    size_t off = ((size_t)b * T_ + t) * C_ + h * D_ + half;
    float xr = q[off], xi = q[off + 32];
    q[off] = xr * c - xi * s;
    q[off + 32] = xr * s + xi * c;
    xr = k[off]; xi = k[off + 32];
    k[off] = xr * c - xi * s;
    k[off + 32] = xr * s + xi * c;
}

// ---------------------------------------------------------------------------
// Tensor-core flash attention (causal, tf32 mma, online softmax).
// CTA: 128 queries x one (b,h). 8 warps; warp owns 16 q rows.
// Key tiles of 64. SMEM stride 72 floats (conflict-free LDS.64 fragments).
// PV computed transposed (yT = Vt * P^T) so P feeds from registers.
// ---------------------------------------------------------------------------
constexpr int ALD2 = 72;
constexpr int ATTN_SMEM2 = (128 + 64 + 64) * ALD2 * 4;  // 73728 B

__global__ __launch_bounds__(256, 2) void attn_mma(
    const float* __restrict__ q, const float* __restrict__ k,
    const float* __restrict__ v, float* __restrict__ y)
{
    extern __shared__ __align__(16) uint32_t sma[];
    uint32_t* Qs = sma;                    // [128][72]
    uint32_t* Ks = sma + 128 * ALD2;       // [64][72]
    uint32_t* Vt = sma + 192 * ALD2;       // [64][72] (V transposed: [d][s])

    const int tid = threadIdx.x;
    const int lane = tid & 31, w = tid >> 5;
    const int r = lane >> 2, kc = lane & 3;
    const int qb = blockIdx.x, bh = blockIdx.y;
    const int b = bh >> 4, h = bh & 15;
    const int q0 = qb * 128;
    const size_t base = ((size_t)b * T_) * C_ + h * D_;

    // Load Q tile (scaled by 1/8, tf32)
#pragma unroll
    for (int it = 0; it < 8; it++) {
        int f = tid + it * 256;
        int row = f >> 4, d4 = f & 15;
        float4 t = *reinterpret_cast<const float4*>(
            &q[base + (size_t)(q0 + row) * C_ + d4 * 4]);
        uint4 u;
        u.x = tf32r(t.x * 0.125f); u.y = tf32r(t.y * 0.125f);
        u.z = tf32r(t.z * 0.125f); u.w = tf32r(t.w * 0.125f);
        *reinterpret_cast<uint4*>(&Qs[row * ALD2 + d4 * 4]) = u;
    }

    float sc[8][4];
    float yacc[4][2][4];
#pragma unroll
    for (int mt = 0; mt < 4; mt++)
#pragma unroll
        for (int nt = 0; nt < 2; nt++)
#pragma unroll
            for (int j = 0; j < 4; j++) yacc[mt][nt][j] = 0.f;
    float mA = -1e30f, mB = -1e30f, lA = 0.f, lB = 0.f;

    const int nit = 2 * qb + 2;
    for (int itk = 0; itk < nit; itk++) {
        const int s0 = itk * 64;
        __syncthreads();
        // Load K tile [64][64] -> Ks (tf32)
#pragma unroll
        for (int i = 0; i < 4; i++) {
            int f = tid + i * 256;
            int row = f >> 4, d4 = f & 15;
            float4 t = *reinterpret_cast<const float4*>(
                &k[base + (size_t)(s0 + row) * C_ + d4 * 4]);
            uint4 u;
            u.x = tf32r(t.x); u.y = tf32r(t.y);
            u.z = tf32r(t.z); u.w = tf32r(t.w);
            *reinterpret_cast<uint4*>(&Ks[row * ALD2 + d4 * 4]) = u;
        }
        // Load V tile transposed -> Vt[d][s] (tf32)
#pragma unroll
        for (int i = 0; i < 4; i++) {
            int f = tid + i * 256;
            int d = f & 63, sb = (f >> 6) * 4;
            const float* vp = &v[base + (size_t)(s0 + sb) * C_ + d];
            uint4 u;
            u.x = tf32r(vp[0]);
            u.y = tf32r(vp[C_]);
            u.z = tf32r(vp[2 * C_]);
            u.w = tf32r(vp[3 * C_]);
            *reinterpret_cast<uint4*>(&Vt[d * ALD2 + sb]) = u;
        }
        __syncthreads();

        const int qrow0 = q0 + 16 * w;       // warp's first q row (global)
        if (s0 > qrow0 + 15) continue;        // fully masked for this warp

        // ---- S = Q K^T (k-slots fed in order 0,2,4,6,1,3,5,7) ----
#pragma unroll
        for (int nt = 0; nt < 8; nt++)
#pragma unroll
            for (int j = 0; j < 4; j++) sc[nt][j] = 0.f;

#pragma unroll
        for (int kk = 0; kk < 8; kk++) {
            uint2 a01 = *reinterpret_cast<const uint2*>(
                &Qs[(16 * w + r) * ALD2 + 8 * kk + 2 * kc]);
            uint2 a23 = *reinterpret_cast<const uint2*>(
                &Qs[(16 * w + r + 8) * ALD2 + 8 * kk + 2 * kc]);
#pragma unroll
            for (int nt = 0; nt < 8; nt++) {
                uint2 bb = *reinterpret_cast<const uint2*>(
                    &Ks[(8 * nt + r) * ALD2 + 8 * kk + 2 * kc]);
                mma_u(sc[nt], a01.x, a23.x, a01.y, a23.y, bb.x, bb.y);
            }
        }

        // ---- causal mask (only near diagonal) ----
        if (s0 + 63 > qrow0) {
            const int qA = qrow0 + r, qB = qA + 8;
#pragma unroll
            for (int nt = 0; nt < 8; nt++) {
                int sg = s0 + 8 * nt + 2 * kc;
                if (sg > qA)     sc[nt][0] = -1e30f;
                if (sg + 1 > qA) sc[nt][1] = -1e30f;
                if (sg > qB)     sc[nt][2] = -1e30f;
                if (sg + 1 > qB) sc[nt][3] = -1e30f;
            }
        }

        // ---- online softmax (rows A=qrow0+r, B=+8; quad lanes share rows) ----
        float mxA = -1e30f, mxB = -1e30f;
#pragma unroll
        for (int nt = 0; nt < 8; nt++) {
            mxA = fmaxf(mxA, fmaxf(sc[nt][0], sc[nt][1]));
            mxB = fmaxf(mxB, fmaxf(sc[nt][2], sc[nt][3]));
        }
        mxA = fmaxf(mxA, __shfl_xor_sync(0xffffffffu, mxA, 1));
        mxA = fmaxf(mxA, __shfl_xor_sync(0xffffffffu, mxA, 2));
        mxB = fmaxf(mxB, __shfl_xor_sync(0xffffffffu, mxB, 1));
        mxB = fmaxf(mxB, __shfl_xor_sync(0xffffffffu, mxB, 2));
        float mnA = fmaxf(mA, mxA), mnB = fmaxf(mB, mxB);
        float cA = __expf(mA - mnA), cB = __expf(mB - mnB);
        mA = mnA; mB = mnB;
        float psA = 0.f, psB = 0.f;
#pragma unroll
        for (int nt = 0; nt < 8; nt++) {
            float p0 = __expf(sc[nt][0] - mnA);
            float p1 = __expf(sc[nt][1] - mnA);
            float p2 = __expf(sc[nt][2] - mnB);
            float p3 = __expf(sc[nt][3] - mnB);
            psA += p0 + p1; psB += p2 + p3;
            sc[nt][0] = p0; sc[nt][1] = p1; sc[nt][2] = p2; sc[nt][3] = p3;
        }
        psA += __shfl_xor_sync(0xffffffffu, psA, 1);
        psA += __shfl_xor_sync(0xffffffffu, psA, 2);
        psB += __shfl_xor_sync(0xffffffffu, psB, 1);
        psB += __shfl_xor_sync(0xffffffffu, psB, 2);
        lA = lA * cA + psA;
        lB = lB * cB + psB;

        // rescale y accumulators (per-column correction via shfl)
        float cc0 = __shfl_sync(0xffffffffu, cA, 8 * kc);
        float cc1 = __shfl_sync(0xffffffffu, cA, 8 * kc + 4);
        float cc2 = __shfl_sync(0xffffffffu, cB, 8 * kc);
        float cc3 = __shfl_sync(0xffffffffu, cB, 8 * kc + 4);
#pragma unroll
        for (int mt = 0; mt < 4; mt++) {
            yacc[mt][0][0] *= cc0; yacc[mt][0][1] *= cc1;
            yacc[mt][0][2] *= cc0; yacc[mt][0][3] *= cc1;
            yacc[mt][1][0] *= cc2; yacc[mt][1][1] *= cc3;
            yacc[mt][1][2] *= cc2; yacc[mt][1][3] *= cc3;
        }

        // ---- convert P to tf32 bits (in place) ----
#pragma unroll
        for (int nt = 0; nt < 8; nt++)
#pragma unroll
            for (int j = 0; j < 4; j++)
                sc[nt][j] = __uint_as_float(tf32r(sc[nt][j]));

        // ---- yT += Vt * P^T  (A = Vt frags, B = P from registers) ----
#pragma unroll
        for (int kk = 0; kk < 8; kk++) {
            uint32_t pb0 = __float_as_uint(sc[kk][0]);
            uint32_t pb1 = __float_as_uint(sc[kk][1]);
            uint32_t pb2 = __float_as_uint(sc[kk][2]);
            uint32_t pb3 = __float_as_uint(sc[kk][3]);
#pragma unroll
            for (int mt = 0; mt < 4; mt++) {
                uint2 v01 = *reinterpret_cast<const uint2*>(
                    &Vt[(16 * mt + r) * ALD2 + 8 * kk + 2 * kc]);
                uint2 v23 = *reinterpret_cast<const uint2*>(
                    &Vt[(16 * mt + r + 8) * ALD2 + 8 * kk + 2 * kc]);
                mma_u(yacc[mt][0], v01.x, v23.x, v01.y, v23.y, pb0, pb1);
                mma_u(yacc[mt][1], v01.x, v23.x, v01.y, v23.y, pb2, pb3);
            }
        }
    }

    // ---- epilogue: normalize, transpose via smem, coalesced store ----
    float iA = 1.f / lA, iB = 1.f / lB;
    float i0 = __shfl_sync(0xffffffffu, iA, 8 * kc);
    float i1 = __shfl_sync(0xffffffffu, iA, 8 * kc + 4);
    float i2 = __shfl_sync(0xffffffffu, iB, 8 * kc);
    float i3 = __shfl_sync(0xffffffffu, iB, 8 * kc + 4);

    __syncthreads();
    float* stg = reinterpret_cast<float*>(Qs);  // reuse: [q 0..127][72]
#pragma unroll
    for (int mt = 0; mt < 4; mt++) {
        const int dr = 16 * mt + r;
#pragma unroll
        for (int nt = 0; nt < 2; nt++) {
            const int qc = 16 * w + 8 * nt + 2 * kc;
            float f0 = (nt ? i2 : i0), f1 = (nt ? i3 : i1);
            stg[qc * ALD2 + dr]           = yacc[mt][nt][0] * f0;
            stg[(qc + 1) * ALD2 + dr]     = yacc[mt][nt][1] * f1;
            stg[qc * ALD2 + dr + 8]       = yacc[mt][nt][2] * f0;
            stg[(qc + 1) * ALD2 + dr + 8] = yacc[mt][nt][3] * f1;
        }
    }
    __syncthreads();
#pragma unroll
    for (int it = 0; it < 8; it++) {
        int f = tid + it * 256;
        int row = f >> 4, d4 = f & 15;
        float4 o = *reinterpret_cast<const float4*>(&stg[row * ALD2 + d4 * 4]);
        *reinterpret_cast<float4*>(
            &y[base + (size_t)(q0 + row) * C_ + d4 * 4]) = o;
    }
}

// ---------------------------------------------------------------------------
// Launch
// ---------------------------------------------------------------------------
extern "C" void kernel_launch(void* const* d_in, const int* in_sizes, int n_in,
                              void* d_out, int out_size)
{
    const float* x  = (const float*)d_in[0];
    const float* wq = (const float*)d_in[1];
    const float* bq = (const float*)d_in[2];
    const float* wk = (const float*)d_in[3];
    const float* bk = (const float*)d_in[4];
    const float* wv = (const float*)d_in[5];
    const float* bv = (const float*)d_in[6];
    const float* wp = (const float*)d_in[7];
    const float* bp = (const float*)d_in[8];
    float* out = (float*)d_out;

    float *qp, *kp, *vp, *yp;
    cudaGetSymbolAddress((void**)&qp, g_q);
    cudaGetSymbolAddress((void**)&kp, g_k);
    cudaGetSymbolAddress((void**)&vp, g_v);
    cudaGetSymbolAddress((void**)&yp, g_y);

    cudaFuncSetAttribute(gemm_mma,
                         cudaFuncAttributeMaxDynamicSharedMemorySize, GEMM_SMEM);
    cudaFuncSetAttribute(attn_mma,
                         cudaFuncAttributeMaxDynamicSharedMemorySize, ATTN_SMEM2);

    dim3 ggrid(C_ / BN, M_ / BM);  // (8, 64)
    gemm_mma<<<ggrid, 256, GEMM_SMEM>>>(x, wq, bq, qp);
    gemm_mma<<<ggrid, 256, GEMM_SMEM>>>(x, wk, bk, kp);
    gemm_mma<<<ggrid, 256, GEMM_SMEM>>>(x, wv, bv, vp);

    rope_kernel<<<(B_ * T_ * H_ * 32) / 256, 256>>>(qp, kp);

    dim3 agrid(16, 64);            // q-tiles x (b*h)
    attn_mma<<<agrid, 256, ATTN_SMEM2>>>(qp, kp, vp, yp);

    gemm_mma<<<ggrid, 256, GEMM_SMEM>>>(yp, wp, bp, out);
}

// round 8
// speedup vs baseline: 4.4906x; 1.0963x over previous
#include <cuda_runtime.h>
#include <cstdint>
#include <math.h>

// Problem shape (fixed)
constexpr int B_ = 4, T_ = 2048, C_ = 1024, H_ = 16, D_ = 64;
constexpr int M_ = B_ * T_;  // 8192

// Scratch (allocations are forbidden; use __device__ globals)
__device__ float g_q[M_ * C_];
__device__ float g_k[M_ * C_];
__device__ float g_v[M_ * C_];
__device__ float g_y[M_ * C_];
__device__ float g_x[M_ * C_];        // tf32-rounded x
__device__ float g_w[4 * C_ * C_];    // tf32-rounded wq|wk|wv|wp

// ---------------------------------------------------------------------------
// helpers
// ---------------------------------------------------------------------------
__device__ __forceinline__ uint32_t smem_u32(const void* p) {
    uint32_t a;
    asm("{ .reg .u64 t; cvta.to.shared.u64 t, %1; cvt.u32.u64 %0, t; }"
        : "=r"(a) : "l"(p));
    return a;
}
__device__ __forceinline__ uint32_t tf32r(float x) {
    uint32_t u;
    asm("cvt.rna.tf32.f32 %0, %1;" : "=r"(u) : "f"(x));
    return u;
}
__device__ __forceinline__ void mma_u(float* c, uint32_t a0, uint32_t a1,
                                      uint32_t a2, uint32_t a3,
                                      uint32_t b0, uint32_t b1) {
    asm volatile(
        "mma.sync.aligned.m16n8k8.row.col.f32.tf32.tf32.f32 "
        "{%0,%1,%2,%3}, {%4,%5,%6,%7}, {%8,%9}, {%0,%1,%2,%3};"
        : "+f"(c[0]), "+f"(c[1]), "+f"(c[2]), "+f"(c[3])
        : "r"(a0), "r"(a1), "r"(a2), "r"(a3), "r"(b0), "r"(b1));
}
#define CP_ASYNC16(dst, src) \
    asm volatile("cp.async.cg.shared.global [%0], [%1], 16;" \
                 :: "r"(dst), "l"(src) : "memory")
#define CP_COMMIT() asm volatile("cp.async.commit_group;" ::: "memory")
#define CP_WAIT0()  asm volatile("cp.async.wait_group 0;" ::: "memory")

// ---------------------------------------------------------------------------
// Pre-round x and the four weight matrices to tf32 (RNA) in gmem, so the
// GEMM can cp.async raw bits and let the MMA truncate exactly.
// ---------------------------------------------------------------------------
__global__ __launch_bounds__(256) void round_tf32(
    const float* __restrict__ x,
    const float* __restrict__ wq, const float* __restrict__ wk,
    const float* __restrict__ wv, const float* __restrict__ wp,
    float* __restrict__ gx, float* __restrict__ gw)
{
    const int XF = M_ * C_ / 4;       // 2097152 float4
    const int WF = C_ * C_ / 4;       // 262144 float4
    int i4 = blockIdx.x * 256 + threadIdx.x;
    const float4* src;
    float4* dst;
    if (i4 < XF) {
        src = reinterpret_cast<const float4*>(x);
        dst = reinterpret_cast<float4*>(gx);
    } else {
        int j = i4 - XF;
        int w = j / WF;
        i4 = j - w * WF;
        const float* ws = (w == 0) ? wq : (w == 1) ? wk : (w == 2) ? wv : wp;
        src = reinterpret_cast<const float4*>(ws);
        dst = reinterpret_cast<float4*>(gw + (size_t)w * C_ * C_);
    }
    float4 t = src[i4];
    uint4 u;
    u.x = tf32r(t.x); u.y = tf32r(t.y); u.z = tf32r(t.z); u.w = tf32r(t.w);
    *reinterpret_cast<uint4*>(&dst[i4]) = u;
}

// ---------------------------------------------------------------------------
// GEMM via mma.sync tf32: out = A*W^T + bias.  A,W pre-rounded to tf32.
// 128x128 tile, BK=32, cp.async double-buffer, ONE barrier per chunk.
// 8 warps (2M x 4N), warp tile 64x32. SMEM stride 40 (==8 mod 32):
// conflict-free LDS.64 fragment loads with even/odd k pairing.
// ---------------------------------------------------------------------------
constexpr int BK = 32, LDSG = 40;
constexpr int TILEG = 128 * LDSG;                 // floats per operand-stage
constexpr int GEMM_SMEM = 4 * TILEG * 4;          // 81920 B

__global__ __launch_bounds__(256, 2) void gemm_mma(
    const float* __restrict__ A, const float* __restrict__ W,
    const float* __restrict__ bias, float* __restrict__ out)
{
    extern __shared__ __align__(16) float smg[];
    const uint32_t sbase = smem_u32(smg);
    const int tid = threadIdx.x;
    const int lane = tid & 31, wid = tid >> 5;
    const int warp_m = wid & 1, warp_n = wid >> 1;
    const int row0 = blockIdx.y * 128, col0 = blockIdx.x * 128;
    const int r = lane >> 2, kc = lane & 3;

    float acc[4][4][4];
#pragma unroll
    for (int i = 0; i < 4; i++)
#pragma unroll
        for (int j = 0; j < 4; j++)
#pragma unroll
            for (int q = 0; q < 4; q++) acc[i][j][q] = 0.f;

    const int lrow = tid >> 3, lc4 = (tid & 7) * 4;
    const float* gA = &A[(size_t)(row0 + lrow) * C_ + lc4];
    const float* gW = &W[(size_t)(col0 + lrow) * C_ + lc4];
    const uint32_t soff = (uint32_t)(lrow * LDSG + lc4) * 4;

    auto issue = [&](int c) {
        const uint32_t sa = sbase + (uint32_t)((c & 1) * TILEG) * 4 + soff;
        const uint32_t sb = sa + (uint32_t)(2 * TILEG) * 4;
        const int k0 = c * BK;
#pragma unroll
        for (int it = 0; it < 4; it++) {
            CP_ASYNC16(sa + (uint32_t)(it * 32 * LDSG) * 4,
                       gA + (size_t)it * 32 * C_ + k0);
            CP_ASYNC16(sb + (uint32_t)(it * 32 * LDSG) * 4,
                       gW + (size_t)it * 32 * C_ + k0);
        }
        CP_COMMIT();
    };

    issue(0);

    const int NCH = C_ / BK;  // 32
    for (int c = 0; c < NCH; c++) {
        CP_WAIT0();
        __syncthreads();
        if (c + 1 < NCH) issue(c + 1);

        const float* as = smg + (c & 1) * TILEG;
        const float* bs = smg + 2 * TILEG + (c & 1) * TILEG;
        const int ar = warp_m * 64 + r;
        const int br = warp_n * 32 + r;

#pragma unroll
        for (int kk = 0; kk < 4; kk++) {
            const int ko = 8 * kk + 2 * kc;
            uint2 a01[4], a23[4];
#pragma unroll
            for (int mt = 0; mt < 4; mt++) {
                a01[mt] = *reinterpret_cast<const uint2*>(
                    &as[(ar + mt * 16) * LDSG + ko]);
                a23[mt] = *reinterpret_cast<const uint2*>(
                    &as[(ar + mt * 16 + 8) * LDSG + ko]);
            }
#pragma unroll
            for (int nt = 0; nt < 4; nt++) {
                uint2 bb = *reinterpret_cast<const uint2*>(
                    &bs[(br + nt * 8) * LDSG + ko]);
#pragma unroll
                for (int mt = 0; mt < 4; mt++)
                    mma_u(acc[mt][nt], a01[mt].x, a23[mt].x,
                          a01[mt].y, a23[mt].y, bb.x, bb.y);
            }
        }
    }

    // Epilogue: bias + direct float2 stores
    const int orow = row0 + warp_m * 64 + r;
    const int ocol = col0 + warp_n * 32 + 2 * kc;
#pragma unroll
    for (int nt = 0; nt < 4; nt++) {
        const int cg = ocol + nt * 8;
        const float b0 = bias[cg], b1 = bias[cg + 1];
#pragma unroll
        for (int mt = 0; mt < 4; mt++) {
            float2 v0 = make_float2(acc[mt][nt][0] + b0, acc[mt][nt][1] + b1);
            float2 v1 = make_float2(acc[mt][nt][2] + b0, acc[mt][nt][3] + b1);
            *reinterpret_cast<float2*>(&out[(size_t)(orow + mt * 16) * C_ + cg]) = v0;
            *reinterpret_cast<float2*>(&out[(size_t)(orow + mt * 16 + 8) * C_ + cg]) = v1;
        }
    }
}

// ---------------------------------------------------------------------------
// RoPE in place on q and k (fp32).
// ---------------------------------------------------------------------------
__global__ __launch_bounds__(256) void rope_kernel(float* __restrict__ q,
                                                   float* __restrict__ k)
{
    int idx = blockIdx.x * 256 + threadIdx.x;
    int half = idx & 31;
    int h = (idx >> 5) & 15;
    int t = (idx >> 9) & 2047;
    int b = idx >> 20;

    float alpha = exp2f(-(float)half * 0.41524101186092029f);
    float ang = (float)t * alpha;
    float c = cosf(ang), s = sinf(ang);

    size_t off = ((size_t)b * T_ + t) * C_ + h * D_ + half;
    float xr = q[off], xi = q[off + 32];
    q[off] = xr * c - xi * s;
    q[off + 32] = xr * s + xi * c;
    xr = k[off]; xi = k[off + 32];
    k[off] = xr * c - xi * s;
    k[off + 32] = xr * s + xi * c;
}

// ---------------------------------------------------------------------------
// Tensor-core flash attention (causal, tf32 mma, online softmax).
// Unchanged from R7, except the final y store is RNA-rounded to tf32 so the
// output-projection GEMM can consume it raw via cp.async.
// ---------------------------------------------------------------------------
constexpr int ALD2 = 72;
constexpr int ATTN_SMEM2 = (128 + 64 + 64) * ALD2 * 4;  // 73728 B

__global__ __launch_bounds__(256, 2) void attn_mma(
    const float* __restrict__ q, const float* __restrict__ k,
    const float* __restrict__ v, float* __restrict__ y)
{
    extern __shared__ __align__(16) uint32_t sma[];
    uint32_t* Qs = sma;                    // [128][72]
    uint32_t* Ks = sma + 128 * ALD2;       // [64][72]
    uint32_t* Vt = sma + 192 * ALD2;       // [64][72] (V transposed: [d][s])

    const int tid = threadIdx.x;
    const int lane = tid & 31, w = tid >> 5;
    const int r = lane >> 2, kc = lane & 3;
    const int qb = blockIdx.x, bh = blockIdx.y;
    const int b = bh >> 4, h = bh & 15;
    const int q0 = qb * 128;
    const size_t base = ((size_t)b * T_) * C_ + h * D_;

    // Load Q tile (scaled by 1/8, tf32)
#pragma unroll
    for (int it = 0; it < 8; it++) {
        int f = tid + it * 256;
        int row = f >> 4, d4 = f & 15;
        float4 t = *reinterpret_cast<const float4*>(
            &q[base + (size_t)(q0 + row) * C_ + d4 * 4]);
        uint4 u;
        u.x = tf32r(t.x * 0.125f); u.y = tf32r(t.y * 0.125f);
        u.z = tf32r(t.z * 0.125f); u.w = tf32r(t.w * 0.125f);
        *reinterpret_cast<uint4*>(&Qs[row * ALD2 + d4 * 4]) = u;
    }

    float sc[8][4];
    float yacc[4][2][4];
#pragma unroll
    for (int mt = 0; mt < 4; mt++)
#pragma unroll
        for (int nt = 0; nt < 2; nt++)
#pragma unroll
            for (int j = 0; j < 4; j++) yacc[mt][nt][j] = 0.f;
    float mA = -1e30f, mB = -1e30f, lA = 0.f, lB = 0.f;

    const int nit = 2 * qb + 2;
    for (int itk = 0; itk < nit; itk++) {
        const int s0 = itk * 64;
        __syncthreads();
        // Load K tile [64][64] -> Ks (tf32)
#pragma unroll
        for (int i = 0; i < 4; i++) {
            int f = tid + i * 256;
            int row = f >> 4, d4 = f & 15;
            float4 t = *reinterpret_cast<const float4*>(
                &k[base + (size_t)(s0 + row) * C_ + d4 * 4]);
            uint4 u;
            u.x = tf32r(t.x); u.y = tf32r(t.y);
            u.z = tf32r(t.z); u.w = tf32r(t.w);
            *reinterpret_cast<uint4*>(&Ks[row * ALD2 + d4 * 4]) = u;
        }
        // Load V tile transposed -> Vt[d][s] (tf32)
#pragma unroll
        for (int i = 0; i < 4; i++) {
            int f = tid + i * 256;
            int d = f & 63, sb = (f >> 6) * 4;
            const float* vp = &v[base + (size_t)(s0 + sb) * C_ + d];
            uint4 u;
            u.x = tf32r(vp[0]);
            u.y = tf32r(vp[C_]);
            u.z = tf32r(vp[2 * C_]);
            u.w = tf32r(vp[3 * C_]);
            *reinterpret_cast<uint4*>(&Vt[d * ALD2 + sb]) = u;
        }
        __syncthreads();

        const int qrow0 = q0 + 16 * w;
        if (s0 > qrow0 + 15) continue;

        // ---- S = Q K^T ----
#pragma unroll
        for (int nt = 0; nt < 8; nt++)
#pragma unroll
            for (int j = 0; j < 4; j++) sc[nt][j] = 0.f;

#pragma unroll
        for (int kk = 0; kk < 8; kk++) {
            uint2 a01 = *reinterpret_cast<const uint2*>(
                &Qs[(16 * w + r) * ALD2 + 8 * kk + 2 * kc]);
            uint2 a23 = *reinterpret_cast<const uint2*>(
                &Qs[(16 * w + r + 8) * ALD2 + 8 * kk + 2 * kc]);
#pragma unroll
            for (int nt = 0; nt < 8; nt++) {
                uint2 bb = *reinterpret_cast<const uint2*>(
                    &Ks[(8 * nt + r) * ALD2 + 8 * kk + 2 * kc]);
                mma_u(sc[nt], a01.x, a23.x, a01.y, a23.y, bb.x, bb.y);
            }
        }

        // ---- causal mask ----
        if (s0 + 63 > qrow0) {
            const int qA = qrow0 + r, qB = qA + 8;
#pragma unroll
            for (int nt = 0; nt < 8; nt++) {
                int sg = s0 + 8 * nt + 2 * kc;
                if (sg > qA)     sc[nt][0] = -1e30f;
                if (sg + 1 > qA) sc[nt][1] = -1e30f;
                if (sg > qB)     sc[nt][2] = -1e30f;
                if (sg + 1 > qB) sc[nt][3] = -1e30f;
            }
        }

        // ---- online softmax ----
        float mxA = -1e30f, mxB = -1e30f;
#pragma unroll
        for (int nt = 0; nt < 8; nt++) {
            mxA = fmaxf(mxA, fmaxf(sc[nt][0], sc[nt][1]));
            mxB = fmaxf(mxB, fmaxf(sc[nt][2], sc[nt][3]));
        }
        mxA = fmaxf(mxA, __shfl_xor_sync(0xffffffffu, mxA, 1));
        mxA = fmaxf(mxA, __shfl_xor_sync(0xffffffffu, mxA, 2));
        mxB = fmaxf(mxB, __shfl_xor_sync(0xffffffffu, mxB, 1));
        mxB = fmaxf(mxB, __shfl_xor_sync(0xffffffffu, mxB, 2));
        float mnA = fmaxf(mA, mxA), mnB = fmaxf(mB, mxB);
        float cA = __expf(mA - mnA), cB = __expf(mB - mnB);
        mA = mnA; mB = mnB;
        float psA = 0.f, psB = 0.f;
#pragma unroll
        for (int nt = 0; nt < 8; nt++) {
            float p0 = __expf(sc[nt][0] - mnA);
            float p1 = __expf(sc[nt][1] - mnA);
            float p2 = __expf(sc[nt][2] - mnB);
            float p3 = __expf(sc[nt][3] - mnB);
            psA += p0 + p1; psB += p2 + p3;
            sc[nt][0] = p0; sc[nt][1] = p1; sc[nt][2] = p2; sc[nt][3] = p3;
        }
        psA += __shfl_xor_sync(0xffffffffu, psA, 1);
        psA += __shfl_xor_sync(0xffffffffu, psA, 2);
        psB += __shfl_xor_sync(0xffffffffu, psB, 1);
        psB += __shfl_xor_sync(0xffffffffu, psB, 2);
        lA = lA * cA + psA;
        lB = lB * cB + psB;

        float cc0 = __shfl_sync(0xffffffffu, cA, 8 * kc);
        float cc1 = __shfl_sync(0xffffffffu, cA, 8 * kc + 4);
        float cc2 = __shfl_sync(0xffffffffu, cB, 8 * kc);
        float cc3 = __shfl_sync(0xffffffffu, cB, 8 * kc + 4);
#pragma unroll
        for (int mt = 0; mt < 4; mt++) {
            yacc[mt][0][0] *= cc0; yacc[mt][0][1] *= cc1;
            yacc[mt][0][2] *= cc0; yacc[mt][0][3] *= cc1;
            yacc[mt][1][0] *= cc2; yacc[mt][1][1] *= cc3;
            yacc[mt][1][2] *= cc2; yacc[mt][1][3] *= cc3;
        }

        // ---- P to tf32 ----
#pragma unroll
        for (int nt = 0; nt < 8; nt++)
#pragma unroll
            for (int j = 0; j < 4; j++)
                sc[nt][j] = __uint_as_float(tf32r(sc[nt][j]));

        // ---- yT += Vt * P^T ----
#pragma unroll
        for (int kk = 0; kk < 8; kk++) {
            uint32_t pb0 = __float_as_uint(sc[kk][0]);
            uint32_t pb1 = __float_as_uint(sc[kk][1]);
            uint32_t pb2 = __float_as_uint(sc[kk][2]);
            uint32_t pb3 = __float_as_uint(sc[kk][3]);
#pragma unroll
            for (int mt = 0; mt < 4; mt++) {
                uint2 v01 = *reinterpret_cast<const uint2*>(
                    &Vt[(16 * mt + r) * ALD2 + 8 * kk + 2 * kc]);
                uint2 v23 = *reinterpret_cast<const uint2*>(
                    &Vt[(16 * mt + r + 8) * ALD2 + 8 * kk + 2 * kc]);
                mma_u(yacc[mt][0], v01.x, v23.x, v01.y, v23.y, pb0, pb1);
                mma_u(yacc[mt][1], v01.x, v23.x, v01.y, v23.y, pb2, pb3);
            }
        }
    }

    // ---- epilogue: normalize, transpose via smem, tf32-rounded store ----
    float iA = 1.f / lA, iB = 1.f / lB;
    float i0 = __shfl_sync(0xffffffffu, iA, 8 * kc);
    float i1 = __shfl_sync(0xffffffffu, iA, 8 * kc + 4);
    float i2 = __shfl_sync(0xffffffffu, iB, 8 * kc);
    float i3 = __shfl_sync(0xffffffffu, iB, 8 * kc + 4);

    __syncthreads();
    float* stg = reinterpret_cast<float*>(Qs);
#pragma unroll
    for (int mt = 0; mt < 4; mt++) {
        const int dr = 16 * mt + r;
#pragma unroll
        for (int nt = 0; nt < 2; nt++) {
            const int qc = 16 * w + 8 * nt + 2 * kc;
            float f0 = (nt ? i2 : i0), f1 = (nt ? i3 : i1);
            stg[qc * ALD2 + dr]           = yacc[mt][nt][0] * f0;
            stg[(qc + 1) * ALD2 + dr]     = yacc[mt][nt][1] * f1;
            stg[qc * ALD2 + dr + 8]       = yacc[mt][nt][2] * f0;
            stg[(qc + 1) * ALD2 + dr + 8] = yacc[mt][nt][3] * f1;
        }
    }
    __syncthreads();
#pragma unroll
    for (int it = 0; it < 8; it++) {
        int f = tid + it * 256;
        int row = f >> 4, d4 = f & 15;
        float4 o = *reinterpret_cast<const float4*>(&stg[row * ALD2 + d4 * 4]);
        uint4 u;
        u.x = tf32r(o.x); u.y = tf32r(o.y); u.z = tf32r(o.z); u.w = tf32r(o.w);
        *reinterpret_cast<uint4*>(
            &y[base + (size_t)(q0 + row) * C_ + d4 * 4]) = u;
    }
}

// ---------------------------------------------------------------------------
// Launch
// ---------------------------------------------------------------------------
extern "C" void kernel_launch(void* const* d_in, const int* in_sizes, int n_in,
                              void* d_out, int out_size)
{
    const float* x  = (const float*)d_in[0];
    const float* wq = (const float*)d_in[1];
    const float* bq = (const float*)d_in[2];
    const float* wk = (const float*)d_in[3];
    const float* bk = (const float*)d_in[4];
    const float* wv = (const float*)d_in[5];
    const float* bv = (const float*)d_in[6];
    const float* wp = (const float*)d_in[7];
    const float* bp = (const float*)d_in[8];
    float* out = (float*)d_out;

    float *qp, *kp, *vp, *yp, *xp, *wr;
    cudaGetSymbolAddress((void**)&qp, g_q);
    cudaGetSymbolAddress((void**)&kp, g_k);
    cudaGetSymbolAddress((void**)&vp, g_v);
    cudaGetSymbolAddress((void**)&yp, g_y);
    cudaGetSymbolAddress((void**)&xp, g_x);
    cudaGetSymbolAddress((void**)&wr, g_w);

    cudaFuncSetAttribute(gemm_mma,
                         cudaFuncAttributeMaxDynamicSharedMemorySize, GEMM_SMEM);
    cudaFuncSetAttribute(attn_mma,
                         cudaFuncAttributeMaxDynamicSharedMemorySize, ATTN_SMEM2);

    // Pre-round x and weights to tf32 (RNA) once.
    const int RBLK = (M_ * C_ / 4 + 4 * C_ * C_ / 4) / 256;  // 12288
    round_tf32<<<RBLK, 256>>>(x, wq, wk, wv, wp, xp, wr);

    dim3 ggrid(C_ / 128, M_ / 128);  // (8, 64)
    gemm_mma<<<ggrid, 256, GEMM_SMEM>>>(xp, wr + 0 * C_ * C_, bq, qp);
    gemm_mma<<<ggrid, 256, GEMM_SMEM>>>(xp, wr + 1 * C_ * C_, bk, kp);
    gemm_mma<<<ggrid, 256, GEMM_SMEM>>>(xp, wr + 2 * C_ * C_, bv, vp);

    rope_kernel<<<(B_ * T_ * H_ * 32) / 256, 256>>>(qp, kp);

    dim3 agrid(16, 64);              // q-tiles x (b*h)
    attn_mma<<<agrid, 256, ATTN_SMEM2>>>(qp, kp, vp, yp);

    gemm_mma<<<ggrid, 256, GEMM_SMEM>>>(yp, wr + 3 * C_ * C_, bp, out);
}